// round 2
// baseline (speedup 1.0000x reference)
#include <cuda_runtime.h>
#include <cstdint>

#define NN 40000
#define EE 640000

// ---------------- device scratch (no allocations allowed) ----------------
__device__ __align__(16) float g_h[(size_t)NN * 160];    // per node: h_s[64] ++ h_v[32*3]
__device__ __align__(16) float g_agg[(size_t)NN * 480];  // per node: agg_s[96] ++ agg_v[128*3]

// ---------------- constants ----------------
static constexpr float INV8        = 0.125f;
static constexpr float INV_SQRT32  = 0.17677669529663687f;
static constexpr float INV_SQRT3   = 0.57735026918962576f;
static constexpr float INV_SQRT2   = 0.70710678118654752f;
static constexpr float INV_SQRT96  = 0.10206207261596575f;
static constexpr float INV_SQRT128 = 0.08838834764831845f;
static constexpr float INV_NN      = 0.25f;   // 1/sqrt(16)

__device__ __forceinline__ float sigmoidf_(float x) { return 1.f / (1.f + __expf(-x)); }
__device__ __forceinline__ float siluf_(float x)    { return x / (1.f + __expf(-x)); }

// ---------------- zero accumulator ----------------
__global__ void zero_kernel() {
    size_t i = (size_t)blockIdx.x * blockDim.x + threadIdx.x;
    size_t total = (size_t)NN * 480 / 4;
    float4* p = reinterpret_cast<float4*>(g_agg);
    if (i < total) p[i] = make_float4(0.f, 0.f, 0.f, 0.f);
}

// ---------------- node pre: h = [s@lin1_ws, v@lin1_wv] ----------------
// persistent: 148 blocks x 640 threads; 32 nodes per chunk; thread = (col u in 0..159, q in 0..3)
__global__ void __launch_bounds__(640) node_pre_kernel(
    const float* __restrict__ nf, const float* __restrict__ na,
    const float* __restrict__ lin1_ws, const float* __restrict__ lin1_wv)
{
    __shared__ float ws[64 * 64];
    __shared__ float wv[32 * 32];
    __shared__ float sv[32 * 160];
    __shared__ float aa[32];
    int t = threadIdx.x;
    for (int i = t; i < 4096; i += 640) ws[i] = lin1_ws[i];
    for (int i = t; i < 1024; i += 640) wv[i] = lin1_wv[i];
    int u = t % 160;
    int q = t / 160;

    for (int chunk = blockIdx.x; chunk < NN / 32; chunk += gridDim.x) {
        int nbase = chunk * 32;
        __syncthreads();
        for (int i = t; i < 32 * 160; i += 640) sv[i] = nf[(size_t)nbase * 160 + i];
        if (t < 32) aa[t] = na[nbase + t];
        __syncthreads();

        if (u < 64) {
            float acc[8];
            #pragma unroll
            for (int k = 0; k < 8; k++) acc[k] = 0.f;
            #pragma unroll
            for (int c = 0; c < 64; c++) {
                float w = ws[c * 64 + u];
                #pragma unroll
                for (int k = 0; k < 8; k++) acc[k] = fmaf(sv[(q * 8 + k) * 160 + c], w, acc[k]);
            }
            #pragma unroll
            for (int k = 0; k < 8; k++) {
                int n = q * 8 + k;
                g_h[(size_t)(nbase + n) * 160 + u] = acc[k] * aa[n] * INV8;
            }
        } else {
            int g = u - 64, d = g / 3, ii = g - d * 3;
            float acc[8];
            #pragma unroll
            for (int k = 0; k < 8; k++) acc[k] = 0.f;
            #pragma unroll
            for (int c = 0; c < 32; c++) {
                float w = wv[c * 32 + d];
                #pragma unroll
                for (int k = 0; k < 8; k++) acc[k] = fmaf(sv[(q * 8 + k) * 160 + 64 + c * 3 + ii], w, acc[k]);
            }
            #pragma unroll
            for (int k = 0; k < 8; k++) {
                int n = q * 8 + k;
                g_h[(size_t)(nbase + n) * 160 + u] = acc[k] * aa[n] * INV_SQRT32;
            }
        }
    }
}

// ---------------- edge kernel: MLP + messages + scatter (fused) ----------------
// persistent: 148 blocks x 1024 threads, 128 edges per tile, ~219KB smem, 32 warps/SM.
// smem (floats): w1 4096 | w2 14336 | es 8192 | hid 8192 | hsv 20480 | ea 512 | src/dst 256
#define ESMEM_FLOATS 56064
#define ESMEM_BYTES  (ESMEM_FLOATS * 4)
#define ETILE 128

__global__ void __launch_bounds__(1024) edge_kernel(
    const float* __restrict__ edge_scalars, const int* __restrict__ edge_src,
    const int* __restrict__ edge_dst, const float* __restrict__ edge_attr,
    const float* __restrict__ fc_w1, const float* __restrict__ fc_w2)
{
    extern __shared__ float sm[];
    float* w1s    = sm;            //  4096 : fc_w1 (64x64)
    float* w2s    = sm + 4096;     // 14336 : fc_w2 (64x224)
    float* es_sm  = sm + 18432;    //  8192 : edge_scalars tile (128x64)
    float* hid_sm = sm + 26624;    //  8192 : hidden (128x64)
    float* hsv_sm = sm + 34816;    // 20480 : gathered h rows (128x160)
    float* ea_sm  = sm + 55296;    //   512 : edge_attr (128x4)
    int*   src_sm = (int*)(sm + 55808);   // 128
    int*   dst_sm = src_sm + 128;         // 128

    int t = threadIdx.x;
    for (int i = t; i < 4096;  i += 1024) w1s[i] = fc_w1[i];
    for (int i = t; i < 14336; i += 1024) w2s[i] = fc_w2[i];

    int p  = t >> 4;      // edge pair 0..63
    int jq = t & 15;      // col quad within 0..15

    for (int tile = blockIdx.x; tile < EE / ETILE; tile += gridDim.x) {
        int base = tile * ETILE;
        __syncthreads();   // protect smem reuse from previous tile

        // ---- phase A: stage edge data ----
        {
            const float4* s4 = reinterpret_cast<const float4*>(edge_scalars + (size_t)base * 64);
            float4* d4 = reinterpret_cast<float4*>(es_sm);
            #pragma unroll
            for (int i = 0; i < 2; i++) d4[t + i * 1024] = s4[t + i * 1024];
            if (t < ETILE) {
                src_sm[t] = edge_src[base + t];
                dst_sm[t] = edge_dst[base + t];
                float4 ea = reinterpret_cast<const float4*>(edge_attr)[base + t];
                ea_sm[t * 4 + 0] = ea.x; ea_sm[t * 4 + 1] = ea.y;
                ea_sm[t * 4 + 2] = ea.z; ea_sm[t * 4 + 3] = ea.w;
            }
        }
        __syncthreads();

        // ---- phase B: gather h rows (float4, L2 resident) overlapped with hidden GEMM ----
        {
            float4* h4 = reinterpret_cast<float4*>(hsv_sm);
            #pragma unroll
            for (int i = 0; i < 5; i++) {
                int idx = t + i * 1024;          // 0..5119
                int e = idx / 40, c4 = idx - e * 40;
                h4[idx] = reinterpret_cast<const float4*>(g_h + (size_t)src_sm[e] * 160)[c4];
            }
        }
        {
            const float* er0 = es_sm + (2 * p) * 64;
            const float* er1 = er0 + 64;
            float a0x = 0, a0y = 0, a0z = 0, a0w = 0;
            float a1x = 0, a1y = 0, a1z = 0, a1w = 0;
            #pragma unroll
            for (int c = 0; c < 64; c++) {
                float4 w = *reinterpret_cast<const float4*>(w1s + c * 64 + jq * 4);
                float x0 = er0[c], x1 = er1[c];
                a0x = fmaf(x0, w.x, a0x); a0y = fmaf(x0, w.y, a0y);
                a0z = fmaf(x0, w.z, a0z); a0w = fmaf(x0, w.w, a0w);
                a1x = fmaf(x1, w.x, a1x); a1y = fmaf(x1, w.y, a1y);
                a1z = fmaf(x1, w.z, a1z); a1w = fmaf(x1, w.w, a1w);
            }
            float* h0 = hid_sm + (2 * p) * 64 + jq * 4;
            h0[0] = siluf_(a0x * INV8); h0[1] = siluf_(a0y * INV8);
            h0[2] = siluf_(a0z * INV8); h0[3] = siluf_(a0w * INV8);
            float* h1 = h0 + 64;
            h1[0] = siluf_(a1x * INV8); h1[1] = siluf_(a1y * INV8);
            h1[2] = siluf_(a1z * INV8); h1[3] = siluf_(a1w * INV8);
        }
        __syncthreads();

        // ---- phase C (fused): w = hid @ fc_w2 in registers -> messages -> float4 scatter ----
        {
            int e0i = 2 * p, e1i = 2 * p + 1;
            const float* hr0 = hid_sm + e0i * 64;
            const float* hr1 = hr0 + 64;
            const float* H0 = hsv_sm + e0i * 160;
            const float* H1 = hsv_sm + e1i * 160;
            float ea00 = ea_sm[e0i * 4 + 0], ea01 = ea_sm[e0i * 4 + 1],
                  ea02 = ea_sm[e0i * 4 + 2], ea03 = ea_sm[e0i * 4 + 3];
            float ea10 = ea_sm[e1i * 4 + 0], ea11 = ea_sm[e1i * 4 + 1],
                  ea12 = ea_sm[e1i * 4 + 2], ea13 = ea_sm[e1i * 4 + 3];
            float* R0 = g_agg + (size_t)dst_sm[e0i] * 480;
            float* R1 = g_agg + (size_t)dst_sm[e1i] * 480;

            for (int jq2 = jq; jq2 < 56; jq2 += 16) {
                int j = jq2 * 4;
                float a0x = 0, a0y = 0, a0z = 0, a0w = 0;
                float a1x = 0, a1y = 0, a1z = 0, a1w = 0;
                #pragma unroll
                for (int c = 0; c < 64; c++) {
                    float4 w = *reinterpret_cast<const float4*>(w2s + c * 224 + j);
                    float x0 = hr0[c], x1 = hr1[c];
                    a0x = fmaf(x0, w.x, a0x); a0y = fmaf(x0, w.y, a0y);
                    a0z = fmaf(x0, w.z, a0z); a0w = fmaf(x0, w.w, a0w);
                    a1x = fmaf(x1, w.x, a1x); a1y = fmaf(x1, w.y, a1y);
                    a1z = fmaf(x1, w.z, a1z); a1w = fmaf(x1, w.w, a1w);
                }
                a0x *= INV8; a0y *= INV8; a0z *= INV8; a0w *= INV8;
                a1x *= INV8; a1y *= INV8; a1z *= INV8; a1w *= INV8;

                if (j < 64) {
                    // m_s1 = w1 * h_s * e0 at [j..j+3]
                    atomicAdd(reinterpret_cast<float4*>(R0 + j),
                        make_float4(a0x * H0[j] * ea00, a0y * H0[j+1] * ea00,
                                    a0z * H0[j+2] * ea00, a0w * H0[j+3] * ea00));
                    atomicAdd(reinterpret_cast<float4*>(R1 + j),
                        make_float4(a1x * H1[j] * ea10, a1y * H1[j+1] * ea10,
                                    a1z * H1[j+2] * ea10, a1w * H1[j+3] * ea10));
                } else if (j < 128) {
                    // m_v1 = (w2 * h_s) outer e1 at [96 + (j-64)*3 ..], 12 floats
                    int d = j - 64;
                    {
                        float c0 = a0x * H0[d], c1 = a0y * H0[d+1], c2 = a0z * H0[d+2], c3 = a0w * H0[d+3];
                        float* o = R0 + 96 + d * 3;
                        atomicAdd(reinterpret_cast<float4*>(o),
                            make_float4(c0*ea01, c0*ea02, c0*ea03, c1*ea01));
                        atomicAdd(reinterpret_cast<float4*>(o + 4),
                            make_float4(c1*ea02, c1*ea03, c2*ea01, c2*ea02));
                        atomicAdd(reinterpret_cast<float4*>(o + 8),
                            make_float4(c2*ea03, c3*ea01, c3*ea02, c3*ea03));
                    }
                    {
                        float c0 = a1x * H1[d], c1 = a1y * H1[d+1], c2 = a1z * H1[d+2], c3 = a1w * H1[d+3];
                        float* o = R1 + 96 + d * 3;
                        atomicAdd(reinterpret_cast<float4*>(o),
                            make_float4(c0*ea11, c0*ea12, c0*ea13, c1*ea11));
                        atomicAdd(reinterpret_cast<float4*>(o + 4),
                            make_float4(c1*ea12, c1*ea13, c2*ea11, c2*ea12));
                        atomicAdd(reinterpret_cast<float4*>(o + 8),
                            make_float4(c2*ea13, c3*ea11, c3*ea12, c3*ea13));
                    }
                } else if (j < 160) {
                    // m_v2 = w3 * ev * e0 at [288 + (j-128)*3 ..], 12 floats
                    int c = j - 128;
                    {
                        const float* A = H0 + 64 + c * 3;
                        float* o = R0 + 288 + c * 3;
                        atomicAdd(reinterpret_cast<float4*>(o),
                            make_float4(a0x*A[0]*ea00, a0x*A[1]*ea00, a0x*A[2]*ea00, a0y*A[3]*ea00));
                        atomicAdd(reinterpret_cast<float4*>(o + 4),
                            make_float4(a0y*A[4]*ea00, a0y*A[5]*ea00, a0z*A[6]*ea00, a0z*A[7]*ea00));
                        atomicAdd(reinterpret_cast<float4*>(o + 8),
                            make_float4(a0z*A[8]*ea00, a0w*A[9]*ea00, a0w*A[10]*ea00, a0w*A[11]*ea00));
                    }
                    {
                        const float* A = H1 + 64 + c * 3;
                        float* o = R1 + 288 + c * 3;
                        atomicAdd(reinterpret_cast<float4*>(o),
                            make_float4(a1x*A[0]*ea10, a1x*A[1]*ea10, a1x*A[2]*ea10, a1y*A[3]*ea10));
                        atomicAdd(reinterpret_cast<float4*>(o + 4),
                            make_float4(a1y*A[4]*ea10, a1y*A[5]*ea10, a1z*A[6]*ea10, a1z*A[7]*ea10));
                        atomicAdd(reinterpret_cast<float4*>(o + 8),
                            make_float4(a1z*A[8]*ea10, a1w*A[9]*ea10, a1w*A[10]*ea10, a1w*A[11]*ea10));
                    }
                } else if (j < 192) {
                    // m_s2 = w4 * (ev . e1) / sqrt(3) at [64 + (j-160) ..], 4 floats
                    int c = j - 160;
                    {
                        const float* A = H0 + 64 + c * 3;
                        atomicAdd(reinterpret_cast<float4*>(R0 + 64 + c), make_float4(
                            a0x * INV_SQRT3 * (A[0]*ea01 + A[1]*ea02 + A[2]*ea03),
                            a0y * INV_SQRT3 * (A[3]*ea01 + A[4]*ea02 + A[5]*ea03),
                            a0z * INV_SQRT3 * (A[6]*ea01 + A[7]*ea02 + A[8]*ea03),
                            a0w * INV_SQRT3 * (A[9]*ea01 + A[10]*ea02 + A[11]*ea03)));
                    }
                    {
                        const float* A = H1 + 64 + c * 3;
                        atomicAdd(reinterpret_cast<float4*>(R1 + 64 + c), make_float4(
                            a1x * INV_SQRT3 * (A[0]*ea11 + A[1]*ea12 + A[2]*ea13),
                            a1y * INV_SQRT3 * (A[3]*ea11 + A[4]*ea12 + A[5]*ea13),
                            a1z * INV_SQRT3 * (A[6]*ea11 + A[7]*ea12 + A[8]*ea13),
                            a1w * INV_SQRT3 * (A[9]*ea11 + A[10]*ea12 + A[11]*ea13)));
                    }
                } else {
                    // m_v3 = w5 * cross(ev, e1) / sqrt(2) at [384 + (j-192)*3 ..], 12 floats
                    int c = j - 192;
                    {
                        const float* A = H0 + 64 + c * 3;
                        float w0 = a0x * INV_SQRT2, w1v = a0y * INV_SQRT2,
                              w2v = a0z * INV_SQRT2, w3v = a0w * INV_SQRT2;
                        float* o = R0 + 384 + c * 3;
                        atomicAdd(reinterpret_cast<float4*>(o), make_float4(
                            w0*(A[1]*ea03 - A[2]*ea02), w0*(A[2]*ea01 - A[0]*ea03),
                            w0*(A[0]*ea02 - A[1]*ea01), w1v*(A[4]*ea03 - A[5]*ea02)));
                        atomicAdd(reinterpret_cast<float4*>(o + 4), make_float4(
                            w1v*(A[5]*ea01 - A[3]*ea03), w1v*(A[3]*ea02 - A[4]*ea01),
                            w2v*(A[7]*ea03 - A[8]*ea02), w2v*(A[8]*ea01 - A[6]*ea03)));
                        atomicAdd(reinterpret_cast<float4*>(o + 8), make_float4(
                            w2v*(A[6]*ea02 - A[7]*ea01), w3v*(A[10]*ea03 - A[11]*ea02),
                            w3v*(A[11]*ea01 - A[9]*ea03), w3v*(A[9]*ea02 - A[10]*ea01)));
                    }
                    {
                        const float* A = H1 + 64 + c * 3;
                        float w0 = a1x * INV_SQRT2, w1v = a1y * INV_SQRT2,
                              w2v = a1z * INV_SQRT2, w3v = a1w * INV_SQRT2;
                        float* o = R1 + 384 + c * 3;
                        atomicAdd(reinterpret_cast<float4*>(o), make_float4(
                            w0*(A[1]*ea13 - A[2]*ea12), w0*(A[2]*ea11 - A[0]*ea13),
                            w0*(A[0]*ea12 - A[1]*ea11), w1v*(A[4]*ea13 - A[5]*ea12)));
                        atomicAdd(reinterpret_cast<float4*>(o + 4), make_float4(
                            w1v*(A[5]*ea11 - A[3]*ea13), w1v*(A[3]*ea12 - A[4]*ea11),
                            w2v*(A[7]*ea13 - A[8]*ea12), w2v*(A[8]*ea11 - A[6]*ea13)));
                        atomicAdd(reinterpret_cast<float4*>(o + 8), make_float4(
                            w2v*(A[6]*ea12 - A[7]*ea11), w3v*(A[10]*ea13 - A[11]*ea12),
                            w3v*(A[11]*ea11 - A[9]*ea13), w3v*(A[9]*ea12 - A[10]*ea11)));
                    }
                }
            }
        }
    }
}

// ---------------- node post: lin2 + self-connection + gating ----------------
// persistent: 148 blocks x 768 threads; 32 nodes per chunk; thread = (unit u in 0..191, q in 0..3)
#define PSMEM_FLOATS 42016
#define PSMEM_BYTES  (PSMEM_FLOATS * 4)

__global__ void __launch_bounds__(768) node_post_kernel(
    const float* __restrict__ nf, const float* __restrict__ na,
    const float* __restrict__ sc_ws, const float* __restrict__ sc_wv,
    const float* __restrict__ lin2_ws, const float* __restrict__ lin2_wv,
    float* __restrict__ out)
{
    extern __shared__ float sm[];
    float* scws  = sm;              //  6144 (64x96)
    float* l2ws  = sm + 6144;       //  9216 (96x96)
    float* scwv  = sm + 15360;      //  1024 (32x32)
    float* l2wv  = sm + 16384;      //  4096 (128x32)
    float* sv    = sm + 20480;      //  5120 (32x160)
    float* ag    = sm + 25600;      // 15360 (32x480)
    float* gates = sm + 40960;      //  1024 (32x32)
    float* aa    = sm + 41984;      //    32

    int t = threadIdx.x;
    for (int i = t; i < 6144; i += 768) scws[i] = sc_ws[i];
    for (int i = t; i < 9216; i += 768) l2ws[i] = lin2_ws[i];
    for (int i = t; i < 1024; i += 768) scwv[i] = sc_wv[i];
    for (int i = t; i < 4096; i += 768) l2wv[i] = lin2_wv[i];
    int u = t % 192, q = t / 192;

    for (int chunk = blockIdx.x; chunk < NN / 32; chunk += gridDim.x) {
        int nbase = chunk * 32;
        __syncthreads();   // protect staging + gates reuse
        for (int i = t; i < 5120; i += 768) sv[i] = nf[(size_t)nbase * 160 + i];
        for (int i = t; i < 15360; i += 768) ag[i] = g_agg[(size_t)nbase * 480 + i];
        if (t < 32) aa[t] = na[nbase + t];
        __syncthreads();

        float pv[8];
        bool is_vec = (u >= 96);
        if (!is_vec) {
            int d = u;
            float acc[8], ac2[8];
            #pragma unroll
            for (int k = 0; k < 8; k++) { acc[k] = 0.f; ac2[k] = 0.f; }
            #pragma unroll
            for (int c = 0; c < 64; c++) {
                float w = scws[c * 96 + d];
                #pragma unroll
                for (int k = 0; k < 8; k++) acc[k] = fmaf(sv[(q * 8 + k) * 160 + c], w, acc[k]);
            }
            #pragma unroll
            for (int c = 0; c < 96; c++) {
                float w = l2ws[c * 96 + d];
                #pragma unroll
                for (int k = 0; k < 8; k++) ac2[k] = fmaf(ag[(q * 8 + k) * 480 + c], w, ac2[k]);
            }
            #pragma unroll
            for (int k = 0; k < 8; k++) {
                int n = q * 8 + k;
                float pre = (acc[k] * INV8 + ac2[k] * (INV_SQRT96 * INV_NN)) * aa[n];
                if (d < 64) out[(size_t)(nbase + n) * 160 + d] = siluf_(pre);
                else        gates[n * 32 + (d - 64)] = sigmoidf_(pre);
            }
        } else {
            int g = u - 96, d = g / 3, ii = g - d * 3;
            float acc[8], ac2[8];
            #pragma unroll
            for (int k = 0; k < 8; k++) { acc[k] = 0.f; ac2[k] = 0.f; }
            #pragma unroll
            for (int c = 0; c < 32; c++) {
                float w = scwv[c * 32 + d];
                #pragma unroll
                for (int k = 0; k < 8; k++) acc[k] = fmaf(sv[(q * 8 + k) * 160 + 64 + c * 3 + ii], w, acc[k]);
            }
            #pragma unroll
            for (int c = 0; c < 128; c++) {
                float w = l2wv[c * 32 + d];
                #pragma unroll
                for (int k = 0; k < 8; k++) ac2[k] = fmaf(ag[(q * 8 + k) * 480 + 96 + c * 3 + ii], w, ac2[k]);
            }
            #pragma unroll
            for (int k = 0; k < 8; k++) {
                int n = q * 8 + k;
                pv[k] = (acc[k] * INV_SQRT32 + ac2[k] * (INV_SQRT128 * INV_NN)) * aa[n];
            }
        }
        __syncthreads();   // gates visible to vector threads
        if (is_vec) {
            int g = u - 96, d = g / 3;
            #pragma unroll
            for (int k = 0; k < 8; k++) {
                int n = q * 8 + k;
                out[(size_t)(nbase + n) * 160 + 64 + g] = gates[n * 32 + d] * pv[k];
            }
        }
    }
}

// ---------------- launch ----------------
extern "C" void kernel_launch(void* const* d_in, const int* in_sizes, int n_in,
                              void* d_out, int out_size)
{
    const float* nf      = (const float*)d_in[0];
    const float* na      = (const float*)d_in[1];
    const int*   esrc    = (const int*)  d_in[2];
    const int*   edst    = (const int*)  d_in[3];
    const float* eattr   = (const float*)d_in[4];
    const float* escal   = (const float*)d_in[5];
    const float* lin1_ws = (const float*)d_in[6];
    const float* lin1_wv = (const float*)d_in[7];
    const float* fc_w1   = (const float*)d_in[8];
    const float* fc_w2   = (const float*)d_in[9];
    const float* sc_ws   = (const float*)d_in[10];
    const float* sc_wv   = (const float*)d_in[11];
    const float* lin2_ws = (const float*)d_in[12];
    const float* lin2_wv = (const float*)d_in[13];
    float* out = (float*)d_out;

    cudaFuncSetAttribute(edge_kernel,      cudaFuncAttributeMaxDynamicSharedMemorySize, ESMEM_BYTES);
    cudaFuncSetAttribute(node_post_kernel, cudaFuncAttributeMaxDynamicSharedMemorySize, PSMEM_BYTES);

    zero_kernel<<<(NN * 480 / 4 + 255) / 256, 256>>>();
    node_pre_kernel<<<148, 640>>>(nf, na, lin1_ws, lin1_wv);
    edge_kernel<<<148, 1024, ESMEM_BYTES>>>(escal, esrc, edst, eattr, fc_w1, fc_w2);
    node_post_kernel<<<148, 768, PSMEM_BYTES>>>(nf, na, sc_ws, sc_wv, lin2_ws, lin2_wv, out);
}

// round 3
// speedup vs baseline: 1.8872x; 1.8872x over previous
#include <cuda_runtime.h>
#include <cstdint>

#define NN 40000
#define EE 640000

// ---------------- device scratch (no allocations allowed) ----------------
__device__ __align__(16) float g_h[(size_t)NN * 160];    // per node: h_s[64] ++ h_v[32*3]
__device__ __align__(16) float g_agg[(size_t)NN * 480];  // per node: agg_s[96] ++ agg_v[128*3]

// ---------------- constants ----------------
static constexpr float INV8        = 0.125f;
static constexpr float INV_SQRT32  = 0.17677669529663687f;
static constexpr float INV_SQRT3   = 0.57735026918962576f;
static constexpr float INV_SQRT2   = 0.70710678118654752f;
static constexpr float INV_SQRT96  = 0.10206207261596575f;
static constexpr float INV_SQRT128 = 0.08838834764831845f;
static constexpr float INV_NN      = 0.25f;   // 1/sqrt(16)

__device__ __forceinline__ float sigmoidf_(float x) { return 1.f / (1.f + __expf(-x)); }
__device__ __forceinline__ float siluf_(float x)    { return x / (1.f + __expf(-x)); }

// ---------------- zero accumulator ----------------
__global__ void zero_kernel() {
    size_t i = (size_t)blockIdx.x * blockDim.x + threadIdx.x;
    size_t total = (size_t)NN * 480 / 4;
    float4* p = reinterpret_cast<float4*>(g_agg);
    if (i < total) p[i] = make_float4(0.f, 0.f, 0.f, 0.f);
}

// ---------------- node pre: h = [s@lin1_ws, v@lin1_wv] ----------------
__global__ void __launch_bounds__(640) node_pre_kernel(
    const float* __restrict__ nf, const float* __restrict__ na,
    const float* __restrict__ lin1_ws, const float* __restrict__ lin1_wv)
{
    __shared__ float ws[64 * 64];
    __shared__ float wv[32 * 32];
    __shared__ float sv[32 * 160];
    __shared__ float aa[32];
    int t = threadIdx.x;
    for (int i = t; i < 4096; i += 640) ws[i] = lin1_ws[i];
    for (int i = t; i < 1024; i += 640) wv[i] = lin1_wv[i];
    int u = t % 160;
    int q = t / 160;

    for (int chunk = blockIdx.x; chunk < NN / 32; chunk += gridDim.x) {
        int nbase = chunk * 32;
        __syncthreads();
        for (int i = t; i < 32 * 160; i += 640) sv[i] = nf[(size_t)nbase * 160 + i];
        if (t < 32) aa[t] = na[nbase + t];
        __syncthreads();

        if (u < 64) {
            float acc[8];
            #pragma unroll
            for (int k = 0; k < 8; k++) acc[k] = 0.f;
            #pragma unroll
            for (int c = 0; c < 64; c++) {
                float w = ws[c * 64 + u];
                #pragma unroll
                for (int k = 0; k < 8; k++) acc[k] = fmaf(sv[(q * 8 + k) * 160 + c], w, acc[k]);
            }
            #pragma unroll
            for (int k = 0; k < 8; k++) {
                int n = q * 8 + k;
                g_h[(size_t)(nbase + n) * 160 + u] = acc[k] * aa[n] * INV8;
            }
        } else {
            int g = u - 64, d = g / 3, ii = g - d * 3;
            float acc[8];
            #pragma unroll
            for (int k = 0; k < 8; k++) acc[k] = 0.f;
            #pragma unroll
            for (int c = 0; c < 32; c++) {
                float w = wv[c * 32 + d];
                #pragma unroll
                for (int k = 0; k < 8; k++) acc[k] = fmaf(sv[(q * 8 + k) * 160 + 64 + c * 3 + ii], w, acc[k]);
            }
            #pragma unroll
            for (int k = 0; k < 8; k++) {
                int n = q * 8 + k;
                g_h[(size_t)(nbase + n) * 160 + u] = acc[k] * aa[n] * INV_SQRT32;
            }
        }
    }
}

// ---------------- edge kernel ----------------
// persistent: 148 blocks x 1024 threads (32 warps), 64 edges/tile, ~202KB smem.
// GEMM phases use transposed activations: warp = (col-quad, 32 consecutive edges)
//   -> weight float4 is a warp broadcast, activation LDS is conflict-free.
// smem (floats):
//   w1s   [0      .. 4096 )  fc_w1 64x64 row-major [c][j]
//   w2s   [4096   .. 18432)  fc_w2 64x224 row-major [c][j]
//   es_t  [18432  .. 22592)  edge_scalars transposed [c][e], stride 65
//   hid_t [22592  .. 26752)  hidden transposed [c][e], stride 65
//   w_sm  [26752  .. 41152)  per-edge weights [e][j], stride 225 (scales folded)
//   hsv   [41152  .. 51392)  gathered h rows [e][160]
//   ea    [51392  .. 51648)  edge_attr 64x4
//   src/dst ints  [51648 .. 51776)
#define ESMEM_FLOATS 51776
#define ESMEM_BYTES  (ESMEM_FLOATS * 4)
#define ETILE 64

__global__ void __launch_bounds__(1024) edge_kernel(
    const float* __restrict__ edge_scalars, const int* __restrict__ edge_src,
    const int* __restrict__ edge_dst, const float* __restrict__ edge_attr,
    const float* __restrict__ fc_w1, const float* __restrict__ fc_w2)
{
    extern __shared__ float sm[];
    float* w1s    = sm;
    float* w2s    = sm + 4096;
    float* es_t   = sm + 18432;
    float* hid_t  = sm + 22592;
    float* w_sm   = sm + 26752;
    float* hsv_sm = sm + 41152;
    float* ea_sm  = sm + 51392;
    int*   src_sm = (int*)(sm + 51648);   // 64
    int*   dst_sm = src_sm + 64;          // 64

    int t = threadIdx.x;
    for (int i = t; i < 4096;  i += 1024) w1s[i] = fc_w1[i];
    for (int i = t; i < 14336; i += 1024) w2s[i] = fc_w2[i];

    int wid  = t >> 5;
    int lane = t & 31;
    int jq   = wid & 15;        // col quad for GEMM1
    int half = wid >> 4;        // edge half
    int eg   = half * 32 + lane; // this thread's edge in GEMM phases

    for (int tile = blockIdx.x; tile < EE / ETILE; tile += gridDim.x) {
        int base = tile * ETILE;
        __syncthreads();   // protect smem reuse from previous tile

        // ---- phase A: stage edge data; transpose edge_scalars into es_t ----
        {
            int e = t >> 4, c4 = t & 15;          // 1024 threads = 64e x 16 quads
            float4 v = reinterpret_cast<const float4*>(edge_scalars + (size_t)base * 64)[t];
            int c = c4 * 4;
            es_t[(c + 0) * 65 + e] = v.x;
            es_t[(c + 1) * 65 + e] = v.y;
            es_t[(c + 2) * 65 + e] = v.z;
            es_t[(c + 3) * 65 + e] = v.w;
            if (t < ETILE) {
                src_sm[t] = edge_src[base + t];
                dst_sm[t] = edge_dst[base + t];
                float4 ea = reinterpret_cast<const float4*>(edge_attr)[base + t];
                ea_sm[t * 4 + 0] = ea.x; ea_sm[t * 4 + 1] = ea.y;
                ea_sm[t * 4 + 2] = ea.z; ea_sm[t * 4 + 3] = ea.w;
            }
        }
        __syncthreads();

        // ---- phase B: gather h rows + GEMM1 (es @ fc_w1, silu) ----
        {
            float4* h4 = reinterpret_cast<float4*>(hsv_sm);
            #pragma unroll
            for (int m = 0; m < 3; m++) {
                int idx = t + m * 1024;           // 2560 float4s
                if (idx < 2560) {
                    int e = idx / 40, c4 = idx - e * 40;
                    h4[idx] = reinterpret_cast<const float4*>(g_h + (size_t)src_sm[e] * 160)[c4];
                }
            }
        }
        {
            float ax = 0.f, ay = 0.f, az = 0.f, aw = 0.f;
            #pragma unroll
            for (int c = 0; c < 64; c++) {
                float4 w = *reinterpret_cast<const float4*>(w1s + c * 64 + jq * 4); // broadcast
                float x = es_t[c * 65 + eg];                                        // conflict-free
                ax = fmaf(x, w.x, ax); ay = fmaf(x, w.y, ay);
                az = fmaf(x, w.z, az); aw = fmaf(x, w.w, aw);
            }
            hid_t[(jq * 4 + 0) * 65 + eg] = siluf_(ax * INV8);
            hid_t[(jq * 4 + 1) * 65 + eg] = siluf_(ay * INV8);
            hid_t[(jq * 4 + 2) * 65 + eg] = siluf_(az * INV8);
            hid_t[(jq * 4 + 3) * 65 + eg] = siluf_(aw * INV8);
        }
        __syncthreads();

        // ---- phase C: GEMM2 (hid @ fc_w2) -> w_sm, scales folded ----
        for (int u = wid; u < 112; u += 32) {     // 56 col quads x 2 edge halves
            int jq2 = u % 56, half2 = u / 56;
            int e2 = half2 * 32 + lane;
            int j = jq2 * 4;
            float ax = 0.f, ay = 0.f, az = 0.f, aw = 0.f;
            #pragma unroll
            for (int c = 0; c < 64; c++) {
                float4 w = *reinterpret_cast<const float4*>(w2s + c * 224 + j);     // broadcast
                float x = hid_t[c * 65 + e2];                                       // conflict-free
                ax = fmaf(x, w.x, ax); ay = fmaf(x, w.y, ay);
                az = fmaf(x, w.z, az); aw = fmaf(x, w.w, aw);
            }
            float scale = INV8;
            if (j >= 192)      scale *= INV_SQRT2;
            else if (j >= 160) scale *= INV_SQRT3;
            float* o = w_sm + e2 * 225 + j;
            o[0] = ax * scale; o[1] = ay * scale; o[2] = az * scale; o[3] = aw * scale;
        }
        __syncthreads();

        // ---- phase D: messages + float4 scatter-add (flat, warp-coherent) ----
        for (int i = t; i < 64 * 120; i += 1024) {
            int e = i / 120, q = i - e * 120;
            int f = q * 4;
            const float* W = w_sm + e * 225;
            const float* H = hsv_sm + e * 160;
            float e0 = ea_sm[e * 4 + 0];
            float b0 = ea_sm[e * 4 + 1], b1 = ea_sm[e * 4 + 2], b2 = ea_sm[e * 4 + 3];
            float v[4];
            if (f < 64) {                               // m_s1 = w1 * es * e0
                #pragma unroll
                for (int u2 = 0; u2 < 4; u2++) v[u2] = W[f + u2] * H[f + u2] * e0;
            } else if (f < 96) {                        // m_s2 = w4 * (ev . e1)   (1/sqrt3 folded)
                #pragma unroll
                for (int u2 = 0; u2 < 4; u2++) {
                    int c = f + u2 - 64;
                    const float* a = H + 64 + c * 3;
                    v[u2] = W[160 + c] * (a[0] * b0 + a[1] * b1 + a[2] * b2);
                }
            } else if (f < 288) {                       // m_v1 = (w2*es) outer e1
                #pragma unroll
                for (int u2 = 0; u2 < 4; u2++) {
                    int g = f + u2 - 96; int d = g / 3; int ii = g - d * 3;
                    float bb = (ii == 0) ? b0 : ((ii == 1) ? b1 : b2);
                    v[u2] = W[64 + d] * H[d] * bb;
                }
            } else if (f < 384) {                       // m_v2 = w3 * ev * e0
                #pragma unroll
                for (int u2 = 0; u2 < 4; u2++) {
                    int g = f + u2 - 288; int c = g / 3;
                    v[u2] = W[128 + c] * H[64 + g] * e0;
                }
            } else {                                    // m_v3 = w5 * cross(ev, e1)  (1/sqrt2 folded)
                #pragma unroll
                for (int u2 = 0; u2 < 4; u2++) {
                    int g = f + u2 - 384; int c = g / 3; int ii = g - c * 3;
                    const float* a = H + 64 + c * 3;
                    float cr;
                    if (ii == 0)      cr = a[1] * b2 - a[2] * b1;
                    else if (ii == 1) cr = a[2] * b0 - a[0] * b2;
                    else              cr = a[0] * b1 - a[1] * b0;
                    v[u2] = W[192 + c] * cr;
                }
            }
            float4* addr = reinterpret_cast<float4*>(g_agg + (size_t)dst_sm[e] * 480 + f);
            atomicAdd(addr, make_float4(v[0], v[1], v[2], v[3]));
        }
    }
}

// ---------------- node post: lin2 + self-connection + gating ----------------
#define PSMEM_FLOATS 42016
#define PSMEM_BYTES  (PSMEM_FLOATS * 4)

__global__ void __launch_bounds__(768) node_post_kernel(
    const float* __restrict__ nf, const float* __restrict__ na,
    const float* __restrict__ sc_ws, const float* __restrict__ sc_wv,
    const float* __restrict__ lin2_ws, const float* __restrict__ lin2_wv,
    float* __restrict__ out)
{
    extern __shared__ float sm[];
    float* scws  = sm;              //  6144 (64x96)
    float* l2ws  = sm + 6144;       //  9216 (96x96)
    float* scwv  = sm + 15360;      //  1024 (32x32)
    float* l2wv  = sm + 16384;      //  4096 (128x32)
    float* sv    = sm + 20480;      //  5120 (32x160)
    float* ag    = sm + 25600;      // 15360 (32x480)
    float* gates = sm + 40960;      //  1024 (32x32)
    float* aa    = sm + 41984;      //    32

    int t = threadIdx.x;
    for (int i = t; i < 6144; i += 768) scws[i] = sc_ws[i];
    for (int i = t; i < 9216; i += 768) l2ws[i] = lin2_ws[i];
    for (int i = t; i < 1024; i += 768) scwv[i] = sc_wv[i];
    for (int i = t; i < 4096; i += 768) l2wv[i] = lin2_wv[i];
    int u = t % 192, q = t / 192;

    for (int chunk = blockIdx.x; chunk < NN / 32; chunk += gridDim.x) {
        int nbase = chunk * 32;
        __syncthreads();
        for (int i = t; i < 5120; i += 768) sv[i] = nf[(size_t)nbase * 160 + i];
        for (int i = t; i < 15360; i += 768) ag[i] = g_agg[(size_t)nbase * 480 + i];
        if (t < 32) aa[t] = na[nbase + t];
        __syncthreads();

        float pv[8];
        bool is_vec = (u >= 96);
        if (!is_vec) {
            int d = u;
            float acc[8], ac2[8];
            #pragma unroll
            for (int k = 0; k < 8; k++) { acc[k] = 0.f; ac2[k] = 0.f; }
            #pragma unroll
            for (int c = 0; c < 64; c++) {
                float w = scws[c * 96 + d];
                #pragma unroll
                for (int k = 0; k < 8; k++) acc[k] = fmaf(sv[(q * 8 + k) * 160 + c], w, acc[k]);
            }
            #pragma unroll
            for (int c = 0; c < 96; c++) {
                float w = l2ws[c * 96 + d];
                #pragma unroll
                for (int k = 0; k < 8; k++) ac2[k] = fmaf(ag[(q * 8 + k) * 480 + c], w, ac2[k]);
            }
            #pragma unroll
            for (int k = 0; k < 8; k++) {
                int n = q * 8 + k;
                float pre = (acc[k] * INV8 + ac2[k] * (INV_SQRT96 * INV_NN)) * aa[n];
                if (d < 64) out[(size_t)(nbase + n) * 160 + d] = siluf_(pre);
                else        gates[n * 32 + (d - 64)] = sigmoidf_(pre);
            }
        } else {
            int g = u - 96, d = g / 3, ii = g - d * 3;
            float acc[8], ac2[8];
            #pragma unroll
            for (int k = 0; k < 8; k++) { acc[k] = 0.f; ac2[k] = 0.f; }
            #pragma unroll
            for (int c = 0; c < 32; c++) {
                float w = scwv[c * 32 + d];
                #pragma unroll
                for (int k = 0; k < 8; k++) acc[k] = fmaf(sv[(q * 8 + k) * 160 + 64 + c * 3 + ii], w, acc[k]);
            }
            #pragma unroll
            for (int c = 0; c < 128; c++) {
                float w = l2wv[c * 32 + d];
                #pragma unroll
                for (int k = 0; k < 8; k++) ac2[k] = fmaf(ag[(q * 8 + k) * 480 + 96 + c * 3 + ii], w, ac2[k]);
            }
            #pragma unroll
            for (int k = 0; k < 8; k++) {
                int n = q * 8 + k;
                pv[k] = (acc[k] * INV_SQRT32 + ac2[k] * (INV_SQRT128 * INV_NN)) * aa[n];
            }
        }
        __syncthreads();
        if (is_vec) {
            int g = u - 96, d = g / 3;
            #pragma unroll
            for (int k = 0; k < 8; k++) {
                int n = q * 8 + k;
                out[(size_t)(nbase + n) * 160 + 64 + g] = gates[n * 32 + d] * pv[k];
            }
        }
    }
}

// ---------------- launch ----------------
extern "C" void kernel_launch(void* const* d_in, const int* in_sizes, int n_in,
                              void* d_out, int out_size)
{
    const float* nf      = (const float*)d_in[0];
    const float* na      = (const float*)d_in[1];
    const int*   esrc    = (const int*)  d_in[2];
    const int*   edst    = (const int*)  d_in[3];
    const float* eattr   = (const float*)d_in[4];
    const float* escal   = (const float*)d_in[5];
    const float* lin1_ws = (const float*)d_in[6];
    const float* lin1_wv = (const float*)d_in[7];
    const float* fc_w1   = (const float*)d_in[8];
    const float* fc_w2   = (const float*)d_in[9];
    const float* sc_ws   = (const float*)d_in[10];
    const float* sc_wv   = (const float*)d_in[11];
    const float* lin2_ws = (const float*)d_in[12];
    const float* lin2_wv = (const float*)d_in[13];
    float* out = (float*)d_out;

    cudaFuncSetAttribute(edge_kernel,      cudaFuncAttributeMaxDynamicSharedMemorySize, ESMEM_BYTES);
    cudaFuncSetAttribute(node_post_kernel, cudaFuncAttributeMaxDynamicSharedMemorySize, PSMEM_BYTES);

    zero_kernel<<<(NN * 480 / 4 + 255) / 256, 256>>>();
    node_pre_kernel<<<148, 640>>>(nf, na, lin1_ws, lin1_wv);
    edge_kernel<<<148, 1024, ESMEM_BYTES>>>(escal, esrc, edst, eattr, fc_w1, fc_w2);
    node_post_kernel<<<148, 768, PSMEM_BYTES>>>(nf, na, sc_ws, sc_wv, lin2_ws, lin2_wv, out);
}

// round 4
// speedup vs baseline: 1.9458x; 1.0311x over previous
#include <cuda_runtime.h>
#include <cstdint>

#define NN 40000
#define EE 640000

// ---------------- device scratch (no allocations allowed) ----------------
__device__ __align__(16) float g_h[(size_t)NN * 160];    // per node: h_s[64] ++ h_v[32*3]
__device__ __align__(16) float g_agg[(size_t)NN * 480];  // per node: agg_s[96] ++ agg_v[128*3]

// ---------------- constants ----------------
static constexpr float INV8        = 0.125f;
static constexpr float INV_SQRT32  = 0.17677669529663687f;
static constexpr float INV_SQRT3   = 0.57735026918962576f;
static constexpr float INV_SQRT2   = 0.70710678118654752f;
static constexpr float INV_SQRT96  = 0.10206207261596575f;
static constexpr float INV_SQRT128 = 0.08838834764831845f;
static constexpr float INV_NN      = 0.25f;   // 1/sqrt(16)

__device__ __forceinline__ float sigmoidf_(float x) { return 1.f / (1.f + __expf(-x)); }
__device__ __forceinline__ float siluf_(float x)    { return x / (1.f + __expf(-x)); }

#define GBAR(id) asm volatile("bar.sync %0, 512;" :: "r"(id) : "memory")

// ---------------- zero accumulator ----------------
__global__ void zero_kernel() {
    size_t i = (size_t)blockIdx.x * blockDim.x + threadIdx.x;
    size_t total = (size_t)NN * 480 / 4;
    float4* p = reinterpret_cast<float4*>(g_agg);
    if (i < total) p[i] = make_float4(0.f, 0.f, 0.f, 0.f);
}

// ---------------- node pre: h = [s@lin1_ws, v@lin1_wv] ----------------
__global__ void __launch_bounds__(640) node_pre_kernel(
    const float* __restrict__ nf, const float* __restrict__ na,
    const float* __restrict__ lin1_ws, const float* __restrict__ lin1_wv)
{
    __shared__ float ws[64 * 64];
    __shared__ float wv[32 * 32];
    __shared__ float sv[32 * 160];
    __shared__ float aa[32];
    int t = threadIdx.x;
    for (int i = t; i < 4096; i += 640) ws[i] = lin1_ws[i];
    for (int i = t; i < 1024; i += 640) wv[i] = lin1_wv[i];
    int u = t % 160;
    int q = t / 160;

    for (int chunk = blockIdx.x; chunk < NN / 32; chunk += gridDim.x) {
        int nbase = chunk * 32;
        __syncthreads();
        for (int i = t; i < 32 * 160; i += 640) sv[i] = nf[(size_t)nbase * 160 + i];
        if (t < 32) aa[t] = na[nbase + t];
        __syncthreads();

        if (u < 64) {
            float acc[8];
            #pragma unroll
            for (int k = 0; k < 8; k++) acc[k] = 0.f;
            #pragma unroll
            for (int c = 0; c < 64; c++) {
                float w = ws[c * 64 + u];
                #pragma unroll
                for (int k = 0; k < 8; k++) acc[k] = fmaf(sv[(q * 8 + k) * 160 + c], w, acc[k]);
            }
            #pragma unroll
            for (int k = 0; k < 8; k++) {
                int n = q * 8 + k;
                g_h[(size_t)(nbase + n) * 160 + u] = acc[k] * aa[n] * INV8;
            }
        } else {
            int g = u - 64, d = g / 3, ii = g - d * 3;
            float acc[8];
            #pragma unroll
            for (int k = 0; k < 8; k++) acc[k] = 0.f;
            #pragma unroll
            for (int c = 0; c < 32; c++) {
                float w = wv[c * 32 + d];
                #pragma unroll
                for (int k = 0; k < 8; k++) acc[k] = fmaf(sv[(q * 8 + k) * 160 + 64 + c * 3 + ii], w, acc[k]);
            }
            #pragma unroll
            for (int k = 0; k < 8; k++) {
                int n = q * 8 + k;
                g_h[(size_t)(nbase + n) * 160 + u] = acc[k] * aa[n] * INV_SQRT32;
            }
        }
    }
}

// ---------------- edge kernel ----------------
// 148 blocks x 1024 threads. Block split into TWO independent 16-warp groups
// (named barriers), each streaming its own 32-edge tiles -> cross-group overlap.
// Warp owns one column-quad across all 32 edges (lane = edge): message branch is
// warp-uniform; GEMM2 results go straight from registers to RED.128 (no w_sm).
//
// per-group smem (floats):  es_t 64x33 | hid_t 64x33 | hsv_t 160x33 | ea_t 4x33 | src/dst 64
#define G_EST   0
#define G_HID   2112
#define G_HSV   4224
#define G_EA    9504
#define G_IDX   9636          // ints: src[32], dst[32]
#define GROUP_FLOATS 9704
#define W_FLOATS 18432        // w1 4096 + w2 14336
#define ESMEM_FLOATS (W_FLOATS + 2 * GROUP_FLOATS)
#define ESMEM_BYTES  (ESMEM_FLOATS * 4)

__global__ void __launch_bounds__(1024) edge_kernel(
    const float* __restrict__ edge_scalars, const int* __restrict__ edge_src,
    const int* __restrict__ edge_dst, const float* __restrict__ edge_attr,
    const float* __restrict__ fc_w1, const float* __restrict__ fc_w2)
{
    extern __shared__ float sm[];
    float* w1s = sm;
    float* w2s = sm + 4096;

    int t = threadIdx.x;
    for (int i = t; i < 4096;  i += 1024) w1s[i] = fc_w1[i];
    for (int i = t; i < 14336; i += 1024) w2s[i] = fc_w2[i];
    __syncthreads();

    int wid  = t >> 5;
    int lane = t & 31;
    int g    = wid >> 4;        // group 0/1
    int gw   = wid & 15;        // warp within group
    int t2   = t & 511;         // tid within group
    int barid = 1 + g;

    float* gb    = sm + W_FLOATS + g * GROUP_FLOATS;
    float* es_t  = gb + G_EST;     // [c][e] stride 33
    float* hid_t = gb + G_HID;     // [c][e] stride 33
    float* hsv_t = gb + G_HSV;     // [c][e] stride 33, c in 0..159
    float* ea_t  = gb + G_EA;      // [k][e] stride 33, k in 0..3
    int*   src_sm = (int*)(gb + G_IDX);
    int*   dst_sm = src_sm + 32;

    // tiles of 32 edges; 2 groups per block
    for (int tile = blockIdx.x * 2 + g; tile < EE / 32; tile += 296) {
        int base = tile * 32;
        GBAR(barid);   // previous tile's CD phase done before overwriting buffers

        // ---- phase A: stage edge data (transposed) ----
        {
            int e = t2 >> 4, c4 = t2 & 15;   // 512 = 32e x 16 quads
            float4 v = reinterpret_cast<const float4*>(edge_scalars + (size_t)base * 64)[t2];
            int c = c4 * 4;
            es_t[(c + 0) * 33 + e] = v.x;
            es_t[(c + 1) * 33 + e] = v.y;
            es_t[(c + 2) * 33 + e] = v.z;
            es_t[(c + 3) * 33 + e] = v.w;
            if (t2 < 32) {
                src_sm[t2] = edge_src[base + t2];
                dst_sm[t2] = edge_dst[base + t2];
                float4 ea = reinterpret_cast<const float4*>(edge_attr)[base + t2];
                ea_t[0 * 33 + t2] = ea.x; ea_t[1 * 33 + t2] = ea.y;
                ea_t[2 * 33 + t2] = ea.z; ea_t[3 * 33 + t2] = ea.w;
            }
        }
        GBAR(barid);

        // ---- phase B: gather h rows (transposed) + GEMM1 ----
        {
            #pragma unroll
            for (int m = 0; m < 3; m++) {
                int idx = t2 + m * 512;            // 1280 float4s
                if (idx < 1280) {
                    int e = idx / 40, c4 = idx - e * 40;
                    float4 v = reinterpret_cast<const float4*>(g_h + (size_t)src_sm[e] * 160)[c4];
                    int c = c4 * 4;
                    hsv_t[(c + 0) * 33 + e] = v.x;
                    hsv_t[(c + 1) * 33 + e] = v.y;
                    hsv_t[(c + 2) * 33 + e] = v.z;
                    hsv_t[(c + 3) * 33 + e] = v.w;
                }
            }
        }
        {
            // warp gw -> column quad gw; lane = edge
            float ax = 0.f, ay = 0.f, az = 0.f, aw = 0.f;
            #pragma unroll
            for (int c = 0; c < 64; c++) {
                float4 w = *reinterpret_cast<const float4*>(w1s + c * 64 + gw * 4); // broadcast
                float x = es_t[c * 33 + lane];                                      // conflict-free
                ax = fmaf(x, w.x, ax); ay = fmaf(x, w.y, ay);
                az = fmaf(x, w.z, az); aw = fmaf(x, w.w, aw);
            }
            hid_t[(gw * 4 + 0) * 33 + lane] = siluf_(ax * INV8);
            hid_t[(gw * 4 + 1) * 33 + lane] = siluf_(ay * INV8);
            hid_t[(gw * 4 + 2) * 33 + lane] = siluf_(az * INV8);
            hid_t[(gw * 4 + 3) * 33 + lane] = siluf_(aw * INV8);
        }
        GBAR(barid);

        // ---- phase C+D fused: GEMM2 column-quad in registers -> messages -> RED.128 ----
        {
            float e0 = ea_t[0 * 33 + lane];
            float b0 = ea_t[1 * 33 + lane], b1 = ea_t[2 * 33 + lane], b2 = ea_t[3 * 33 + lane];
            float* R = g_agg + (size_t)dst_sm[lane] * 480;
            const float* H = hsv_t;   // H(c) = hsv_t[c*33 + lane]
            #define HC(c) H[(c) * 33 + lane]

            for (int jq = gw; jq < 56; jq += 16) {
                int j = jq * 4;
                float ax = 0.f, ay = 0.f, az = 0.f, aw = 0.f;
                #pragma unroll
                for (int c = 0; c < 64; c++) {
                    float4 w = *reinterpret_cast<const float4*>(w2s + c * 224 + j); // broadcast
                    float x = hid_t[c * 33 + lane];                                 // conflict-free
                    ax = fmaf(x, w.x, ax); ay = fmaf(x, w.y, ay);
                    az = fmaf(x, w.z, az); aw = fmaf(x, w.w, aw);
                }
                float scale = INV8;
                if (j >= 192)      scale *= INV_SQRT2;
                else if (j >= 160) scale *= INV_SQRT3;
                ax *= scale; ay *= scale; az *= scale; aw *= scale;

                if (j < 64) {
                    // m_s1 = w1 * h_s * e0  -> agg[j..j+3]
                    atomicAdd(reinterpret_cast<float4*>(R + j), make_float4(
                        ax * HC(j) * e0, ay * HC(j + 1) * e0,
                        az * HC(j + 2) * e0, aw * HC(j + 3) * e0));
                } else if (j < 128) {
                    // m_v1 = (w2 * h_s) outer e1  -> agg[96 + d*3 ..], 12 floats
                    int d = j - 64;
                    float c0 = ax * HC(d), c1 = ay * HC(d + 1), c2 = az * HC(d + 2), c3 = aw * HC(d + 3);
                    float* o = R + 96 + d * 3;
                    atomicAdd(reinterpret_cast<float4*>(o),     make_float4(c0*b0, c0*b1, c0*b2, c1*b0));
                    atomicAdd(reinterpret_cast<float4*>(o + 4), make_float4(c1*b1, c1*b2, c2*b0, c2*b1));
                    atomicAdd(reinterpret_cast<float4*>(o + 8), make_float4(c2*b2, c3*b0, c3*b1, c3*b2));
                } else if (j < 160) {
                    // m_v2 = w3 * ev * e0  -> agg[288 + c*3 ..], 12 floats
                    int c = j - 128;
                    int hb = 64 + c * 3;
                    float* o = R + 288 + c * 3;
                    atomicAdd(reinterpret_cast<float4*>(o), make_float4(
                        ax * HC(hb + 0) * e0, ax * HC(hb + 1) * e0,
                        ax * HC(hb + 2) * e0, ay * HC(hb + 3) * e0));
                    atomicAdd(reinterpret_cast<float4*>(o + 4), make_float4(
                        ay * HC(hb + 4) * e0, ay * HC(hb + 5) * e0,
                        az * HC(hb + 6) * e0, az * HC(hb + 7) * e0));
                    atomicAdd(reinterpret_cast<float4*>(o + 8), make_float4(
                        az * HC(hb + 8) * e0, aw * HC(hb + 9) * e0,
                        aw * HC(hb + 10) * e0, aw * HC(hb + 11) * e0));
                } else if (j < 192) {
                    // m_s2 = w4 * (ev . e1)  (1/sqrt3 folded)  -> agg[64 + c ..+3]
                    int c = j - 160;
                    int hb = 64 + c * 3;
                    atomicAdd(reinterpret_cast<float4*>(R + 64 + c), make_float4(
                        ax * (HC(hb+0)*b0 + HC(hb+1)*b1 + HC(hb+2)*b2),
                        ay * (HC(hb+3)*b0 + HC(hb+4)*b1 + HC(hb+5)*b2),
                        az * (HC(hb+6)*b0 + HC(hb+7)*b1 + HC(hb+8)*b2),
                        aw * (HC(hb+9)*b0 + HC(hb+10)*b1 + HC(hb+11)*b2)));
                } else {
                    // m_v3 = w5 * cross(ev, e1)  (1/sqrt2 folded)  -> agg[384 + c*3 ..], 12 floats
                    int c = j - 192;
                    int hb = 64 + c * 3;
                    float a0, a1, a2;
                    float* o = R + 384 + c * 3;
                    a0 = HC(hb+0); a1 = HC(hb+1); a2 = HC(hb+2);
                    float x0 = ax*(a1*b2 - a2*b1), x1 = ax*(a2*b0 - a0*b2), x2 = ax*(a0*b1 - a1*b0);
                    a0 = HC(hb+3); a1 = HC(hb+4); a2 = HC(hb+5);
                    float y0 = ay*(a1*b2 - a2*b1), y1 = ay*(a2*b0 - a0*b2), y2 = ay*(a0*b1 - a1*b0);
                    atomicAdd(reinterpret_cast<float4*>(o), make_float4(x0, x1, x2, y0));
                    a0 = HC(hb+6); a1 = HC(hb+7); a2 = HC(hb+8);
                    float z0 = az*(a1*b2 - a2*b1), z1 = az*(a2*b0 - a0*b2), z2 = az*(a0*b1 - a1*b0);
                    atomicAdd(reinterpret_cast<float4*>(o + 4), make_float4(y1, y2, z0, z1));
                    a0 = HC(hb+9); a1 = HC(hb+10); a2 = HC(hb+11);
                    atomicAdd(reinterpret_cast<float4*>(o + 8), make_float4(
                        z2, aw*(a1*b2 - a2*b1), aw*(a2*b0 - a0*b2), aw*(a0*b1 - a1*b0)));
                }
            }
            #undef HC
        }
    }
}

// ---------------- node post: lin2 + self-connection + gating ----------------
#define PSMEM_FLOATS 42016
#define PSMEM_BYTES  (PSMEM_FLOATS * 4)

__global__ void __launch_bounds__(768) node_post_kernel(
    const float* __restrict__ nf, const float* __restrict__ na,
    const float* __restrict__ sc_ws, const float* __restrict__ sc_wv,
    const float* __restrict__ lin2_ws, const float* __restrict__ lin2_wv,
    float* __restrict__ out)
{
    extern __shared__ float sm[];
    float* scws  = sm;              //  6144 (64x96)
    float* l2ws  = sm + 6144;       //  9216 (96x96)
    float* scwv  = sm + 15360;      //  1024 (32x32)
    float* l2wv  = sm + 16384;      //  4096 (128x32)
    float* sv    = sm + 20480;      //  5120 (32x160)
    float* ag    = sm + 25600;      // 15360 (32x480)
    float* gates = sm + 40960;      //  1024 (32x32)
    float* aa    = sm + 41984;      //    32

    int t = threadIdx.x;
    for (int i = t; i < 6144; i += 768) scws[i] = sc_ws[i];
    for (int i = t; i < 9216; i += 768) l2ws[i] = lin2_ws[i];
    for (int i = t; i < 1024; i += 768) scwv[i] = sc_wv[i];
    for (int i = t; i < 4096; i += 768) l2wv[i] = lin2_wv[i];
    int u = t % 192, q = t / 192;

    for (int chunk = blockIdx.x; chunk < NN / 32; chunk += gridDim.x) {
        int nbase = chunk * 32;
        __syncthreads();
        for (int i = t; i < 5120; i += 768) sv[i] = nf[(size_t)nbase * 160 + i];
        for (int i = t; i < 15360; i += 768) ag[i] = g_agg[(size_t)nbase * 480 + i];
        if (t < 32) aa[t] = na[nbase + t];
        __syncthreads();

        float pv[8];
        bool is_vec = (u >= 96);
        if (!is_vec) {
            int d = u;
            float acc[8], ac2[8];
            #pragma unroll
            for (int k = 0; k < 8; k++) { acc[k] = 0.f; ac2[k] = 0.f; }
            #pragma unroll
            for (int c = 0; c < 64; c++) {
                float w = scws[c * 96 + d];
                #pragma unroll
                for (int k = 0; k < 8; k++) acc[k] = fmaf(sv[(q * 8 + k) * 160 + c], w, acc[k]);
            }
            #pragma unroll
            for (int c = 0; c < 96; c++) {
                float w = l2ws[c * 96 + d];
                #pragma unroll
                for (int k = 0; k < 8; k++) ac2[k] = fmaf(ag[(q * 8 + k) * 480 + c], w, ac2[k]);
            }
            #pragma unroll
            for (int k = 0; k < 8; k++) {
                int n = q * 8 + k;
                float pre = (acc[k] * INV8 + ac2[k] * (INV_SQRT96 * INV_NN)) * aa[n];
                if (d < 64) out[(size_t)(nbase + n) * 160 + d] = siluf_(pre);
                else        gates[n * 32 + (d - 64)] = sigmoidf_(pre);
            }
        } else {
            int g = u - 96, d = g / 3, ii = g - d * 3;
            float acc[8], ac2[8];
            #pragma unroll
            for (int k = 0; k < 8; k++) { acc[k] = 0.f; ac2[k] = 0.f; }
            #pragma unroll
            for (int c = 0; c < 32; c++) {
                float w = scwv[c * 32 + d];
                #pragma unroll
                for (int k = 0; k < 8; k++) acc[k] = fmaf(sv[(q * 8 + k) * 160 + 64 + c * 3 + ii], w, acc[k]);
            }
            #pragma unroll
            for (int c = 0; c < 128; c++) {
                float w = l2wv[c * 32 + d];
                #pragma unroll
                for (int k = 0; k < 8; k++) ac2[k] = fmaf(ag[(q * 8 + k) * 480 + 96 + c * 3 + ii], w, ac2[k]);
            }
            #pragma unroll
            for (int k = 0; k < 8; k++) {
                int n = q * 8 + k;
                pv[k] = (acc[k] * INV_SQRT32 + ac2[k] * (INV_SQRT128 * INV_NN)) * aa[n];
            }
        }
        __syncthreads();
        if (is_vec) {
            int g = u - 96, d = g / 3;
            #pragma unroll
            for (int k = 0; k < 8; k++) {
                int n = q * 8 + k;
                out[(size_t)(nbase + n) * 160 + 64 + g] = gates[n * 32 + d] * pv[k];
            }
        }
    }
}

// ---------------- launch ----------------
extern "C" void kernel_launch(void* const* d_in, const int* in_sizes, int n_in,
                              void* d_out, int out_size)
{
    const float* nf      = (const float*)d_in[0];
    const float* na      = (const float*)d_in[1];
    const int*   esrc    = (const int*)  d_in[2];
    const int*   edst    = (const int*)  d_in[3];
    const float* eattr   = (const float*)d_in[4];
    const float* escal   = (const float*)d_in[5];
    const float* lin1_ws = (const float*)d_in[6];
    const float* lin1_wv = (const float*)d_in[7];
    const float* fc_w1   = (const float*)d_in[8];
    const float* fc_w2   = (const float*)d_in[9];
    const float* sc_ws   = (const float*)d_in[10];
    const float* sc_wv   = (const float*)d_in[11];
    const float* lin2_ws = (const float*)d_in[12];
    const float* lin2_wv = (const float*)d_in[13];
    float* out = (float*)d_out;

    cudaFuncSetAttribute(edge_kernel,      cudaFuncAttributeMaxDynamicSharedMemorySize, ESMEM_BYTES);
    cudaFuncSetAttribute(node_post_kernel, cudaFuncAttributeMaxDynamicSharedMemorySize, PSMEM_BYTES);

    zero_kernel<<<(NN * 480 / 4 + 255) / 256, 256>>>();
    node_pre_kernel<<<148, 640>>>(nf, na, lin1_ws, lin1_wv);
    edge_kernel<<<148, 1024, ESMEM_BYTES>>>(escal, esrc, edst, eattr, fc_w1, fc_w2);
    node_post_kernel<<<148, 768, PSMEM_BYTES>>>(nf, na, sc_ws, sc_wv, lin2_ws, lin2_wv, out);
}